// round 17
// baseline (speedup 1.0000x reference)
#include <cuda_runtime.h>
#include <cuda_bf16.h>

#define NAB 256
#define NAGN 16384
#define NTOT 16640
#define DDIM 128
#define GSZ 2048

typedef unsigned long long ull;

// ---------------- scratch (device globals; no allocation) ----------------
__device__ float g_h[NTOT * DDIM];
__device__ float g_y[NTOT * DDIM];
__device__ float g_z[NTOT * DDIM];
__device__ float g_als[NTOT];
__device__ float g_ald[NTOT];
__device__ float g_zsum[2 * NAB];        // ping-pong per layer
__device__ float g_sum[2 * DDIM];
__device__ float g_ssq[2 * DDIM];
__device__ float g_sumAB[2 * DDIM];
__device__ float g_ssqAB[2 * DDIM];
__device__ float4 g_wimg[4][2176];   // [layer*2 + (hi/lo)] : 128 rows x 272B bf16 images

__device__ __forceinline__ float lrelu(float e) { return e > 0.f ? e : 0.2f * e; }

// ---- packed f32x2 helpers (Blackwell FFMA2) ----
__device__ __forceinline__ ull dup2(float s) {
    ull d; unsigned u = __float_as_uint(s);
    asm("mov.b64 %0, {%1, %1};" : "=l"(d) : "r"(u));
    return d;
}
__device__ __forceinline__ void ffma2(ull& acc, ull a, ull b) {
    asm("fma.rn.f32x2 %0, %1, %2, %0;" : "+l"(acc) : "l"(a), "l"(b));
}
__device__ __forceinline__ void unpk(float& lo, float& hi, ull v) {
    unsigned a, b;
    asm("mov.b64 {%0, %1}, %2;" : "=r"(a), "=r"(b) : "l"(v));
    lo = __uint_as_float(a); hi = __uint_as_float(b);
}

// ---- bf16 HMMA (sm_80 PTX; runs on sm_103 fallback HMMA tensor path) ----
__device__ __forceinline__ void mma_bf16(float* d, const unsigned* a,
                                         unsigned b0, unsigned b1) {
    asm volatile(
        "mma.sync.aligned.m16n8k16.row.col.f32.bf16.bf16.f32 "
        "{%0,%1,%2,%3}, {%4,%5,%6,%7}, {%8,%9}, {%0,%1,%2,%3};\n"
        : "+f"(d[0]), "+f"(d[1]), "+f"(d[2]), "+f"(d[3])
        : "r"(a[0]), "r"(a[1]), "r"(a[2]), "r"(a[3]), "r"(b0), "r"(b1));
}

__device__ __forceinline__ void ldsm4(unsigned* r, unsigned addr) {
    asm volatile("ldmatrix.sync.aligned.m8n8.x4.shared.b16 {%0,%1,%2,%3}, [%4];"
        : "=r"(r[0]), "=r"(r[1]), "=r"(r[2]), "=r"(r[3]) : "r"(addr));
}

__device__ __forceinline__ unsigned smem_u32(const void* p) {
    unsigned a;
    asm("{ .reg .u64 t; cvta.to.shared.u64 t, %1; cvt.u32.u64 %0, t; }" : "=r"(a) : "l"(p));
    return a;
}

#define CPA16(dst, src) \
    asm volatile("cp.async.cg.shared.global [%0], [%1], 16;" \
        :: "r"((unsigned)(dst)), "l"(src) : "memory")

#define RSTR 272            // smem/global image row stride bytes (136 bf16)

// ---------------- prep: split W1/W2 into bf16 hi/lo images [n][k], once ----------------
__global__ void k_prep(const float* __restrict__ W1, const float* __restrict__ W2) {
    const int layer = blockIdx.x >> 2, q = blockIdx.x & 3;
    const float* W = layer ? W2 : W1;
    char* hi_img = (char*)g_wimg[layer * 2];
    char* lo_img = (char*)g_wimg[layer * 2 + 1];
    for (int i = threadIdx.x; i < 2048; i += 256) {
        int n = i & 127, kk = q * 16 + (i >> 7);
        float w0 = W[(size_t)(2 * kk) * 128 + n];
        float w1 = W[(size_t)(2 * kk + 1) * 128 + n];
        __nv_bfloat16 h0 = __float2bfloat16(w0), h1 = __float2bfloat16(w1);
        float l0 = w0 - __bfloat162float(h0), l1 = w1 - __bfloat162float(h1);
        union { __nv_bfloat162 v; unsigned u; } ph, pl;
        ph.v = __halves2bfloat162(h0, h1);
        pl.v = __halves2bfloat162(__float2bfloat16(l0), __float2bfloat16(l1));
        *(unsigned*)(hi_img + n * RSTR + 4 * kk) = ph.u;
        *(unsigned*)(lo_img + n * RSTR + 4 * kk) = pl.u;
    }
}

// ---------------- GEMM via split-bf16 HMMA + ldmatrix, single fused k-loop ----------------
#define SX_H 0
#define SX_L 17408
#define SW_H 34816
#define SW_L 69632
#define S_AS 104448
#define S_AD 104960
#define S_LS 105472
#define S_LD 105728
#define S_ES 105984
#define S_IV 106240
#define SMEM_GEMM 106496

__global__ void __launch_bounds__(256, 2)
k_gemm(const float* __restrict__ X0, const float* __restrict__ X1,
       const float4* __restrict__ wh, const float4* __restrict__ wl,
       const float* __restrict__ asrc, const float* __restrict__ adst,
       float* __restrict__ H, float* __restrict__ ALS, float* __restrict__ ALD,
       float* __restrict__ yz,
       const float* __restrict__ hprev, const float* __restrict__ alsp,
       const float* __restrict__ aldp, const float* __restrict__ biasp,
       const float* __restrict__ zsrd, float* __restrict__ zswr, int fin) {
    extern __shared__ char smem[];
    float* as_sh = (float*)(smem + S_AS);
    float* ad_sh = (float*)(smem + S_AD);
    float* sALS  = (float*)(smem + S_LS);
    float* sALD  = (float*)(smem + S_LD);
    float* sEs   = (float*)(smem + S_ES);
    float* sInv  = (float*)(smem + S_IV);
    const int t = threadIdx.x;
    const int row0 = blockIdx.x * 64;
    const unsigned sb = smem_u32(smem);

    // ---- start W hi/lo image copies early via cp.async ----
    {
        const char* srcH = (const char*)wh;
        const char* srcL = (const char*)wl;
        const unsigned dH = sb + SW_H + t * 16;
        const unsigned dL = sb + SW_L + t * 16;
#pragma unroll
        for (int i = 0; i < 8; i++) {
            CPA16(dH + i * 4096, srcH + (size_t)t * 16 + i * 4096);
            CPA16(dL + i * 4096, srcL + (size_t)t * 16 + i * 4096);
        }
        if (t < 128) {
            CPA16(sb + SW_H + (t + 2048) * 16, srcH + (size_t)(t + 2048) * 16);
            CPA16(sb + SW_L + (t + 2048) * 16, srcL + (size_t)(t + 2048) * 16);
        }
        asm volatile("cp.async.commit_group;" ::: "memory");
    }

    // zero AB region of aggregation target; block 0 zeroes zsum (and BN acc when fin)
    if (row0 < NAB) {
        float4* z4 = reinterpret_cast<float4*>(yz) + row0 * 32;
#pragma unroll
        for (int i = 0; i < 8; i++) z4[t + 256 * i] = make_float4(0.f, 0.f, 0.f, 0.f);
        if (blockIdx.x == 0) {
            zswr[t] = 0.f;
            if (fin) {
                g_sum[t] = 0.f;   g_ssq[t] = 0.f;
                g_sumAB[t] = 0.f; g_ssqAB[t] = 0.f;
            }
        }
    }

    if (t < 128) { as_sh[t] = asrc[t]; ad_sh[t] = adst[t]; }
    if (t < 64) { sALS[t] = 0.f; sALD[t] = 0.f; }

    const int dofin = fin && (row0 < NAB);
    if (dofin) {
        if (t < 64) {
            int row = row0 + t;
            float e = __expf(lrelu(alsp[row] + aldp[row]));
            sEs[t] = e;
            sInv[t] = 1.f / (zsrd[row] + e + 1e-16f);
        }
        __syncthreads();
    }

    // ---- split X tile (64 rows) into bf16 hi/lo, row-major [r][k] ----
    const float* X = (row0 < NAB) ? (X0 + (size_t)row0 * DDIM)
                                  : (X1 + (size_t)(row0 - NAB) * DDIM);
#pragma unroll
    for (int i0 = 0; i0 < 8; i0++) {
        int i = t + 256 * i0;
        int r = i >> 5, kk = (i & 31) * 2;
        float4 x = *(const float4*)(X + (size_t)r * 128 + 2 * kk);
        if (dofin) {
            float4 hh = *(const float4*)(hprev + (size_t)(row0 + r) * 128 + 2 * kk);
            float4 bb = *(const float4*)(biasp + 2 * kk);
            x.x = fmaxf((x.x + sEs[r] * hh.x) * sInv[r] + bb.x, 0.f);
            x.y = fmaxf((x.y + sEs[r] * hh.y) * sInv[r] + bb.y, 0.f);
            x.z = fmaxf((x.z + sEs[r] * hh.z) * sInv[r] + bb.z, 0.f);
            x.w = fmaxf((x.w + sEs[r] * hh.w) * sInv[r] + bb.w, 0.f);
        }
        __nv_bfloat16 h0 = __float2bfloat16(x.x), h1 = __float2bfloat16(x.y);
        __nv_bfloat16 h2 = __float2bfloat16(x.z), h3 = __float2bfloat16(x.w);
        float l0 = x.x - __bfloat162float(h0), l1 = x.y - __bfloat162float(h1);
        float l2 = x.z - __bfloat162float(h2), l3 = x.w - __bfloat162float(h3);
        union { __nv_bfloat162 v; unsigned u; } p0, p1, q0, q1;
        p0.v = __halves2bfloat162(h0, h1);
        p1.v = __halves2bfloat162(h2, h3);
        q0.v = __halves2bfloat162(__float2bfloat16(l0), __float2bfloat16(l1));
        q1.v = __halves2bfloat162(__float2bfloat16(l2), __float2bfloat16(l3));
        *(uint2*)(smem + SX_H + r * RSTR + 4 * kk) = make_uint2(p0.u, p1.u);
        *(uint2*)(smem + SX_L + r * RSTR + 4 * kk) = make_uint2(q0.u, q1.u);
    }
    asm volatile("cp.async.wait_group 0;" ::: "memory");
    __syncthreads();

    const int wid = t >> 5, lane = t & 31;
    const int g = lane >> 2, c = lane & 3;
    const int mrow0 = (wid >> 2) * 32;
    const int ncol0 = (wid & 3) * 32;

    float acc[2][4][4];
#pragma unroll
    for (int mt = 0; mt < 2; mt++)
#pragma unroll
        for (int nt = 0; nt < 4; nt++)
#pragma unroll
            for (int q = 0; q < 4; q++) acc[mt][nt][q] = 0.f;

    const unsigned aoff = (unsigned)((mrow0 + (lane & 15)) * RSTR + ((lane >> 4) << 4));
    const unsigned boff = (unsigned)((ncol0 + ((lane >> 4) << 3) + (lane & 7)) * RSTR
                                     + (((lane >> 3) & 1) << 4));
    const unsigned Ah = sb + SX_H + aoff, Al = sb + SX_L + aoff;
    const unsigned Bh = sb + SW_H + boff, Bl = sb + SW_L + boff;

#pragma unroll 2
    for (int k0 = 0; k0 < 8; k0++) {
        const unsigned ka = k0 * 32;
        unsigned ah[2][4], al[2][4], bh[2][4], bl[2][4];
        ldsm4(ah[0], Ah + ka);
        ldsm4(ah[1], Ah + 16 * RSTR + ka);
        ldsm4(bh[0], Bh + ka);
        ldsm4(bh[1], Bh + 16 * RSTR + ka);
        ldsm4(al[0], Al + ka);
        ldsm4(al[1], Al + 16 * RSTR + ka);
        ldsm4(bl[0], Bl + ka);
        ldsm4(bl[1], Bl + 16 * RSTR + ka);
#pragma unroll
        for (int mt = 0; mt < 2; mt++) {
            mma_bf16(acc[mt][0], ah[mt], bh[0][0], bh[0][1]);
            mma_bf16(acc[mt][1], ah[mt], bh[0][2], bh[0][3]);
            mma_bf16(acc[mt][2], ah[mt], bh[1][0], bh[1][1]);
            mma_bf16(acc[mt][3], ah[mt], bh[1][2], bh[1][3]);
            mma_bf16(acc[mt][0], ah[mt], bl[0][0], bl[0][1]);
            mma_bf16(acc[mt][1], ah[mt], bl[0][2], bl[0][3]);
            mma_bf16(acc[mt][2], ah[mt], bl[1][0], bl[1][1]);
            mma_bf16(acc[mt][3], ah[mt], bl[1][2], bl[1][3]);
            mma_bf16(acc[mt][0], al[mt], bh[0][0], bh[0][1]);
            mma_bf16(acc[mt][1], al[mt], bh[0][2], bh[0][3]);
            mma_bf16(acc[mt][2], al[mt], bh[1][0], bh[1][1]);
            mma_bf16(acc[mt][3], al[mt], bh[1][2], bh[1][3]);
        }
    }

    // ---- epilogue: H stores + per-row als/ald dots ----
#pragma unroll
    for (int mt = 0; mt < 2; mt++) {
        const int rA = mrow0 + mt * 16 + g;
        const int rB = rA + 8;
        float psA = 0.f, pdA = 0.f, psB = 0.f, pdB = 0.f;
#pragma unroll
        for (int nt = 0; nt < 4; nt++) {
            const int C = ncol0 + nt * 8 + 2 * c;
            float d0 = acc[mt][nt][0], d1 = acc[mt][nt][1];
            float d2 = acc[mt][nt][2], d3 = acc[mt][nt][3];
            *(float2*)(H + (size_t)(row0 + rA) * DDIM + C) = make_float2(d0, d1);
            *(float2*)(H + (size_t)(row0 + rB) * DDIM + C) = make_float2(d2, d3);
            float a0 = as_sh[C], a1 = as_sh[C + 1];
            float e0 = ad_sh[C], e1 = ad_sh[C + 1];
            psA += d0 * a0 + d1 * a1;  pdA += d0 * e0 + d1 * e1;
            psB += d2 * a0 + d3 * a1;  pdB += d2 * e0 + d3 * e1;
        }
#pragma unroll
        for (int off = 1; off <= 2; off <<= 1) {
            psA += __shfl_xor_sync(0xffffffffu, psA, off);
            pdA += __shfl_xor_sync(0xffffffffu, pdA, off);
            psB += __shfl_xor_sync(0xffffffffu, psB, off);
            pdB += __shfl_xor_sync(0xffffffffu, pdB, off);
        }
        if (c == 0) {
            atomicAdd(&sALS[rA], psA); atomicAdd(&sALD[rA], pdA);
            atomicAdd(&sALS[rB], psB); atomicAdd(&sALD[rB], pdB);
        }
    }
    __syncthreads();
    if (t < 64) {
        ALS[row0 + t] = sALS[t];
        ALD[row0 + t] = sALD[t];
    }
}

// ---------------- fused aggregation + softmax ----------------
// blocks 0..255: AB dsts (FFMA2 path). blocks 256..511: AG dsts via split-bf16 HMMA,
// 64 dsts/block: out = alpha[64x32] @ h_ab[32x128] + self, normalized.
#define AG_HTH 0
#define AG_HTL 10240
#define AG_WH  20480
#define AG_WL  25600
#define AG_Z   30720
#define AG_ES  31040
#define AG_INV 31360
#define ASTR 80

__global__ void __launch_bounds__(256, 3)
k_agg(const float* __restrict__ h, const float* __restrict__ als,
      const float* __restrict__ ald, const float* __restrict__ bias,
      float* __restrict__ y, float* __restrict__ zsum, int do_relu) {
    __shared__ __align__(16) char sagg[32768];
    float* sbig = (float*)sagg;
    __shared__ float ssmall[16];
    const int t = threadIdx.x;

    if (blockIdx.x < 256) {
        // -------- AB dsts (unchanged FFMA2 path) --------
        const int blk = blockIdx.x;
        const int b = blk >> 5, q = (blk >> 2) & 7, dq = blk & 3;
        const int base = NAB + b * GSZ + q * 256;
        const int d0 = b * 32 + dq * 8;
        float* ald_sh = ssmall;
        float* szs = ssmall + 8;
        if (t < 8) { ald_sh[t] = ald[d0 + t]; szs[t] = 0.f; }
        __syncthreads();
        {
            const int dme = t & 7;
            const float aldme = ald_sh[dme];
            float zloc = 0.f;
#pragma unroll
            for (int i = 0; i < 8; i++) {
                int idx = t + 256 * i;
                int j = idx >> 3;
                float e = __expf(lrelu(als[base + j] + aldme));
                sbig[idx] = e;
                zloc += e;
            }
            atomicAdd(&szs[dme], zloc);
        }
        __syncthreads();
        if (t < 8) atomicAdd(&zsum[d0 + t], szs[t]);

        const int c4 = t & 31, rs = t >> 5;
        ull acc2[4][4];
#pragma unroll
        for (int dp = 0; dp < 4; dp++)
#pragma unroll
            for (int c = 0; c < 4; c++) acc2[dp][c] = 0ull;

        const float4* h4 = reinterpret_cast<const float4*>(h) + (size_t)base * 32 + c4;
        const ull* w8 = reinterpret_cast<const ull*>(sbig);
#pragma unroll 8
        for (int jj = 0; jj < 32; jj++) {
            const int j = rs * 32 + jj;
            float4 hv = h4[(size_t)j * 32];
            ull hd0 = dup2(hv.x), hd1 = dup2(hv.y), hd2 = dup2(hv.z), hd3 = dup2(hv.w);
#pragma unroll
            for (int dp = 0; dp < 4; dp++) {
                ull a = w8[j * 4 + dp];
                ffma2(acc2[dp][0], a, hd0); ffma2(acc2[dp][1], a, hd1);
                ffma2(acc2[dp][2], a, hd2); ffma2(acc2[dp][3], a, hd3);
            }
        }
        __syncthreads();
        float4* st4 = reinterpret_cast<float4*>(sbig) + rs * 256;
#pragma unroll
        for (int dp = 0; dp < 4; dp++) {
            float4 ve, vo;
            unpk(ve.x, vo.x, acc2[dp][0]);
            unpk(ve.y, vo.y, acc2[dp][1]);
            unpk(ve.z, vo.z, acc2[dp][2]);
            unpk(ve.w, vo.w, acc2[dp][3]);
            st4[(2 * dp) * 32 + c4] = ve;
            st4[(2 * dp + 1) * 32 + c4] = vo;
        }
        __syncthreads();
        float s0 = 0.f, s1 = 0.f, s2 = 0.f, s3 = 0.f;
#pragma unroll
        for (int rr = 0; rr < 8; rr++) {
            float4 v = reinterpret_cast<const float4*>(sbig)[rr * 256 + t];
            s0 += v.x; s1 += v.y; s2 += v.z; s3 += v.w;
        }
        const int d = t >> 5, c = (t & 31) * 4;
        float* yo = y + (size_t)(d0 + d) * DDIM + c;
        atomicAdd(yo + 0, s0); atomicAdd(yo + 1, s1);
        atomicAdd(yo + 2, s2); atomicAdd(yo + 3, s3);
    } else {
        // -------- AG dsts via HMMA: 64 dsts per block --------
        const int ablk = blockIdx.x - 256;
        const int b = ablk >> 5, chunk = ablk & 31;
        const int j0 = NAB + b * GSZ + chunk * 64;
        float* zsh = (float*)(sagg + AG_Z);
        float* esh = (float*)(sagg + AG_ES);
        float* ivh = (float*)(sagg + AG_INV);

        if (t < 64) {
            zsh[t] = 0.f;
            esh[t] = __expf(lrelu(als[j0 + t] + ald[j0 + t]));
        }
        __syncthreads();

        // stage 1: weight images alpha[64 dst][32 src], split bf16 hi/lo
        {
            const int d = t & 63;
            const int l0 = (t >> 6) << 3;
            const float aldd = ald[j0 + d];
            const float* alsb = als + b * 32 + l0;
            float e[8];
            float zloc = 0.f;
#pragma unroll
            for (int i = 0; i < 8; i++) {
                e[i] = __expf(lrelu(alsb[i] + aldd));
                zloc += e[i];
            }
            unsigned uh[4], ul[4];
#pragma unroll
            for (int i = 0; i < 4; i++) {
                __nv_bfloat16 h0 = __float2bfloat16(e[2 * i]);
                __nv_bfloat16 h1 = __float2bfloat16(e[2 * i + 1]);
                float l0f = e[2 * i] - __bfloat162float(h0);
                float l1f = e[2 * i + 1] - __bfloat162float(h1);
                union { __nv_bfloat162 v; unsigned u; } ph, pl;
                ph.v = __halves2bfloat162(h0, h1);
                pl.v = __halves2bfloat162(__float2bfloat16(l0f), __float2bfloat16(l1f));
                uh[i] = ph.u; ul[i] = pl.u;
            }
            *(uint4*)(sagg + AG_WH + d * ASTR + l0 * 2) = make_uint4(uh[0], uh[1], uh[2], uh[3]);
            *(uint4*)(sagg + AG_WL + d * ASTR + l0 * 2) = make_uint4(ul[0], ul[1], ul[2], ul[3]);
            atomicAdd(&zsh[d], zloc);
        }

        // stage 2: h_ab transposed images [col][src], split bf16 hi/lo
#pragma unroll
        for (int it = 0; it < 16; it++) {
            int i = t + 256 * it;
            int l = i >> 7, c = i & 127;
            float v = h[(size_t)(b * 32 + l) * DDIM + c];
            __nv_bfloat16 vh = __float2bfloat16(v);
            float vl = v - __bfloat162float(vh);
            *(__nv_bfloat16*)(sagg + AG_HTH + c * ASTR + l * 2) = vh;
            *(__nv_bfloat16*)(sagg + AG_HTL + c * ASTR + l * 2) = __float2bfloat16(vl);
        }
        __syncthreads();
        if (t < 64) ivh[t] = 1.f / (zsh[t] + esh[t] + 1e-16f);
        __syncthreads();

        // stage 3: MMA. warp tile m16 x n64; 2 k16 steps.
        const int wid = t >> 5, lane = t & 31;
        const int g = lane >> 2, c4 = lane & 3;
        const int mrow0 = (wid >> 1) * 16;
        const int ncol0 = (wid & 1) * 64;
        const unsigned sb = smem_u32(sagg);
        const unsigned aoff = (unsigned)((mrow0 + (lane & 15)) * ASTR + ((lane >> 4) << 4));
        const unsigned boff = (unsigned)((ncol0 + ((lane >> 4) << 3) + (lane & 7)) * ASTR
                                         + (((lane >> 3) & 1) << 4));
        const unsigned Ah = sb + AG_WH + aoff, Al = sb + AG_WL + aoff;
        const unsigned Bh = sb + AG_HTH + boff, Bl = sb + AG_HTL + boff;

        float acc[8][4];
#pragma unroll
        for (int nt = 0; nt < 8; nt++)
#pragma unroll
            for (int q = 0; q < 4; q++) acc[nt][q] = 0.f;

#pragma unroll
        for (int k0 = 0; k0 < 2; k0++) {
            const unsigned ka = k0 * 32;
            unsigned ah[4], al[4];
            ldsm4(ah, Ah + ka);
            ldsm4(al, Al + ka);
#pragma unroll
            for (int q = 0; q < 4; q++) {
                unsigned bh[4], bl[4];
                ldsm4(bh, Bh + q * (16 * ASTR) + ka);
                ldsm4(bl, Bl + q * (16 * ASTR) + ka);
                mma_bf16(acc[2 * q],     ah, bh[0], bh[1]);
                mma_bf16(acc[2 * q + 1], ah, bh[2], bh[3]);
                mma_bf16(acc[2 * q],     ah, bl[0], bl[1]);
                mma_bf16(acc[2 * q + 1], ah, bl[2], bl[3]);
                mma_bf16(acc[2 * q],     al, bh[0], bh[1]);
                mma_bf16(acc[2 * q + 1], al, bh[2], bh[3]);
            }
        }

        // epilogue: self term + normalize + bias (+relu), store
        const int rA = mrow0 + g, rB = rA + 8;
        const float esA = esh[rA], ivA = ivh[rA];
        const float esB = esh[rB], ivB = ivh[rB];
        const float* hA = h + (size_t)(j0 + rA) * DDIM;
        const float* hB = h + (size_t)(j0 + rB) * DDIM;
        float* yA = y + (size_t)(j0 + rA) * DDIM;
        float* yB = y + (size_t)(j0 + rB) * DDIM;
#pragma unroll
        for (int nt = 0; nt < 8; nt++) {
            const int C = ncol0 + nt * 8 + 2 * c4;
            float2 ha = *(const float2*)(hA + C);
            float2 hb = *(const float2*)(hB + C);
            float2 bb = *(const float2*)(bias + C);
            float2 ra, rb;
            ra.x = (acc[nt][0] + esA * ha.x) * ivA + bb.x;
            ra.y = (acc[nt][1] + esA * ha.y) * ivA + bb.y;
            rb.x = (acc[nt][2] + esB * hb.x) * ivB + bb.x;
            rb.y = (acc[nt][3] + esB * hb.y) * ivB + bb.y;
            if (do_relu) {
                ra.x = fmaxf(ra.x, 0.f); ra.y = fmaxf(ra.y, 0.f);
                rb.x = fmaxf(rb.x, 0.f); rb.y = fmaxf(rb.y, 0.f);
            }
            *(float2*)(yA + C) = ra;
            *(float2*)(yB + C) = rb;
        }
    }
}

// ---------------- BN stats (layer-2 AB rows finalized on the fly, never stored) ----------------
__global__ void __launch_bounds__(256, 4)
k_stats(const float* __restrict__ z, const float* __restrict__ h,
        const float* __restrict__ als, const float* __restrict__ ald,
        const float* __restrict__ bias, const float* __restrict__ zsum,
        const float* __restrict__ ab, const float* __restrict__ ag) {
    __shared__ float sEs[64], sInv[64];
    const int t = threadIdx.x;
    float s = 0.f, ss = 0.f;
    if (blockIdx.x < 4) {
        const int r0 = blockIdx.x * 64;
        if (t < 64) {
            int row = r0 + t;
            float e = __expf(lrelu(als[row] + ald[row]));
            sEs[t] = e;
            sInv[t] = 1.f / (zsum[row] + e + 1e-16f);
        }
        __syncthreads();
        if (t < 128) {
            const float bc = bias[t];
            for (int r = 0; r < 64; r++) {
                size_t gi = (size_t)(r0 + r) * DDIM + t;
                float v = (z[gi] + sEs[r] * h[gi]) * sInv[r] + bc;
                s += v; ss += v * v;
            }
        } else {
            const int c = t - 128;
            for (int r = 0; r < 64; r++) {
                float v = ab[(size_t)(r0 + r) * DDIM + c];
                s += v; ss += v * v;
            }
        }
        atomicAdd(&g_sumAB[t], s);
        atomicAdd(&g_ssqAB[t], ss);
    } else {
        const int r0 = (blockIdx.x - 4) * 64;
        const float* src = (t < 128) ? (z + (size_t)(NAB + r0) * DDIM + t)
                                     : (ag + (size_t)r0 * DDIM + t - 128);
        for (int r = 0; r < 64; r++) {
            float v = src[(size_t)r * DDIM];
            s += v; ss += v * v;
        }
        atomicAdd(&g_sum[t], s);
        atomicAdd(&g_ssq[t], ss);
    }
}

__device__ __forceinline__ void bnss(float s, float q, float g, float b, float invn,
                                     float& sc, float& sh) {
    float mean = s * invn;
    float var = q * invn - mean * mean;
    sc = g * rsqrtf(var + 1e-5f);
    sh = b - mean * sc;
}

// ---------------- fused BN -> ReLU -> FC epilogue (AB rows finalized inline) ----------------
__global__ void k_apply(float* __restrict__ out,
                        const float* __restrict__ ab, const float* __restrict__ ag,
                        const float* __restrict__ fcw, const float* __restrict__ fcb,
                        const float* __restrict__ agw, const float* __restrict__ agb,
                        const float* __restrict__ gab, const float* __restrict__ bab,
                        const float* __restrict__ gag, const float* __restrict__ bag,
                        const float* __restrict__ als, const float* __restrict__ ald,
                        const float* __restrict__ zsum, const float* __restrict__ h,
                        const float* __restrict__ b2) {
    const int row = blockIdx.x * 8 + (threadIdx.x >> 5);
    const int l = threadIdx.x & 31;
    float4 v1 = reinterpret_cast<const float4*>(g_z + (size_t)row * DDIM)[l];
    float4 v2 = (row < NAB)
        ? reinterpret_cast<const float4*>(ab + (size_t)row * DDIM)[l]
        : reinterpret_cast<const float4*>(ag + (size_t)(row - NAB) * DDIM)[l];

    const float* psum; const float* pssq; const float* pg; const float* pb;
    const float* w; float fb; float invn;
    if (row < NAB) {
        float e = __expf(lrelu(als[row] + ald[row]));
        float inv = 1.f / (zsum[row] + e + 1e-16f);
        float4 hv = reinterpret_cast<const float4*>(h + (size_t)row * DDIM)[l];
        float4 bb = reinterpret_cast<const float4*>(b2)[l];
        v1.x = (v1.x + e * hv.x) * inv + bb.x;
        v1.y = (v1.y + e * hv.y) * inv + bb.y;
        v1.z = (v1.z + e * hv.z) * inv + bb.z;
        v1.w = (v1.w + e * hv.w) * inv + bb.w;
        psum = g_sumAB; pssq = g_ssqAB; pg = gab; pb = bab;
        w = fcw; fb = fcb[0]; invn = 1.f / (float)NAB;
    } else {
        psum = g_sum; pssq = g_ssq; pg = gag; pb = bag;
        w = agw; fb = agb[0]; invn = 1.f / (float)NAGN;
    }
    float4 s1 = reinterpret_cast<const float4*>(psum)[l];
    float4 q1 = reinterpret_cast<const float4*>(pssq)[l];
    float4 s2 = reinterpret_cast<const float4*>(psum)[32 + l];
    float4 q2 = reinterpret_cast<const float4*>(pssq)[32 + l];
    float4 gA = reinterpret_cast<const float4*>(pg)[l];
    float4 bA = reinterpret_cast<const float4*>(pb)[l];
    float4 gB = reinterpret_cast<const float4*>(pg)[32 + l];
    float4 bB = reinterpret_cast<const float4*>(pb)[32 + l];
    float4 scA, shAv, scB, shB;
    bnss(s1.x, q1.x, gA.x, bA.x, invn, scA.x, shAv.x);
    bnss(s1.y, q1.y, gA.y, bA.y, invn, scA.y, shAv.y);
    bnss(s1.z, q1.z, gA.z, bA.z, invn, scA.z, shAv.z);
    bnss(s1.w, q1.w, gA.w, bA.w, invn, scA.w, shAv.w);
    bnss(s2.x, q2.x, gB.x, bB.x, invn, scB.x, shB.x);
    bnss(s2.y, q2.y, gB.y, bB.y, invn, scB.y, shB.y);
    bnss(s2.z, q2.z, gB.z, bB.z, invn, scB.z, shB.z);
    bnss(s2.w, q2.w, gB.w, bB.w, invn, scB.w, shB.w);

    float4 w1 = reinterpret_cast<const float4*>(w)[l];
    float4 w2 = reinterpret_cast<const float4*>(w)[32 + l];
    float sum = 0.f;
    sum += fmaxf(v1.x * scA.x + shAv.x, 0.f) * w1.x;
    sum += fmaxf(v1.y * scA.y + shAv.y, 0.f) * w1.y;
    sum += fmaxf(v1.z * scA.z + shAv.z, 0.f) * w1.z;
    sum += fmaxf(v1.w * scA.w + shAv.w, 0.f) * w1.w;
    sum += fmaxf(v2.x * scB.x + shB.x, 0.f) * w2.x;
    sum += fmaxf(v2.y * scB.y + shB.y, 0.f) * w2.y;
    sum += fmaxf(v2.z * scB.z + shB.z, 0.f) * w2.z;
    sum += fmaxf(v2.w * scB.w + shB.w, 0.f) * w2.w;
#pragma unroll
    for (int off = 16; off; off >>= 1) sum += __shfl_xor_sync(0xffffffffu, sum, off);
    if (l == 0) out[row] = sum + fb;
}

// ---------------- host ----------------
extern "C" void kernel_launch(void* const* d_in, const int* in_sizes, int n_in,
                              void* d_out, int out_size) {
    const float* ab  = (const float*)d_in[0];
    const float* ag  = (const float*)d_in[1];
    const float* W1  = (const float*)d_in[2];
    const float* as1 = (const float*)d_in[3];
    const float* ad1 = (const float*)d_in[4];
    const float* b1  = (const float*)d_in[5];
    const float* W2  = (const float*)d_in[6];
    const float* as2 = (const float*)d_in[7];
    const float* ad2 = (const float*)d_in[8];
    const float* b2  = (const float*)d_in[9];
    const float* gab = (const float*)d_in[10];
    const float* bab = (const float*)d_in[11];
    const float* gag = (const float*)d_in[12];
    const float* bag = (const float*)d_in[13];
    const float* fcw = (const float*)d_in[14];
    const float* fcb = (const float*)d_in[15];
    const float* agw = (const float*)d_in[16];
    const float* agb = (const float*)d_in[17];
    float* out = (float*)d_out;

    float *ph, *py, *pz, *pals, *pald, *pzs;
    float4* pw;
    cudaGetSymbolAddress((void**)&ph, g_h);
    cudaGetSymbolAddress((void**)&py, g_y);
    cudaGetSymbolAddress((void**)&pz, g_z);
    cudaGetSymbolAddress((void**)&pals, g_als);
    cudaGetSymbolAddress((void**)&pald, g_ald);
    cudaGetSymbolAddress((void**)&pzs, g_zsum);
    cudaGetSymbolAddress((void**)&pw, g_wimg);

    cudaFuncSetAttribute(k_gemm, cudaFuncAttributeMaxDynamicSharedMemorySize, SMEM_GEMM);

    k_prep<<<8, 256>>>(W1, W2);

    // ---- layer 1 ----
    k_gemm<<<260, 256, SMEM_GEMM>>>(ab, ag, pw, pw + 2176, as1, ad1, ph, pals, pald, py,
                                    ph, pals, pald, b1, pzs, pzs, 0);
    k_agg<<<512, 256>>>(ph, pals, pald, b1, py, pzs, 1);

    // ---- layer 2 (gemm finalizes layer-1 AB rows inline) ----
    k_gemm<<<260, 256, SMEM_GEMM>>>(py, py + NAB * DDIM, pw + 4352, pw + 6528,
                                    as2, ad2, ph, pals, pald, pz,
                                    ph, pals, pald, b1, pzs, pzs + NAB, 1);
    k_agg<<<512, 256>>>(ph, pals, pald, b2, pz, pzs + NAB, 0);

    // ---- BN stats (AB finalized on the fly) + FC epilogue ----
    k_stats<<<260, 256>>>(pz, ph, pals, pald, b2, pzs + NAB, ab, ag);
    k_apply<<<2080, 256>>>(out, ab, ag, fcw, fcb, agw, agb, gab, bab, gag, bag,
                           pals, pald, pzs + NAB, ph, b2);
}